// round 14
// baseline (speedup 1.0000x reference)
#include <cuda_runtime.h>

#define Bn 64
#define Dd 32
#define Hh 48
#define Ww 48
#define NA (Dd*Hh*Ww)        /* 73728 anchors per batch */
#define TOPK 60
#define NMS_TOPK 20
#define THRESH 0.15f
#define NMS_T 0.05f
#define NBINS 4096
#define NT 1024
#define CB 98304             /* bulk chunk bytes (3 x 96KB = whole batch) */
#define CF4 (CB/16)          /* 6144 float4 per chunk */
#define JPT (CF4/NT)         /* 6 float4 per thread per chunk */
#define DYN_BYTES (2*CB)     /* two 96KB smem buffers */
#define CAND_FB 2304
#define T_RAW 2.9f

__device__ __forceinline__ unsigned fkey(float f) {
    unsigned u = __float_as_uint(f);
    return u ^ ((u & 0x80000000u) ? 0xFFFFFFFFu : 0x80000000u);
}
__device__ __forceinline__ float finv(unsigned k) {
    unsigned u = (k & 0x80000000u) ? (k ^ 0x80000000u) : ~k;
    return __uint_as_float(u);
}
__device__ __forceinline__ unsigned smem_u32(const void* p) {
    unsigned a;
    asm("{ .reg .u64 t; cvta.to.shared.u64 t, %1; cvt.u32.u64 %0, t; }"
        : "=r"(a) : "l"(p));
    return a;
}
__device__ __forceinline__ void mbar_init(unsigned mbar, unsigned cnt) {
    asm volatile("mbarrier.init.shared.b64 [%0], %1;" :: "r"(mbar), "r"(cnt) : "memory");
}
__device__ __forceinline__ void mbar_expect_tx(unsigned mbar, unsigned bytes) {
    asm volatile("mbarrier.arrive.expect_tx.shared.b64 _, [%0], %1;"
                 :: "r"(mbar), "r"(bytes) : "memory");
}
__device__ __forceinline__ void bulk_g2s(unsigned dst, const void* src,
                                         unsigned bytes, unsigned mbar) {
    asm volatile("cp.async.bulk.shared::cluster.global.mbarrier::complete_tx::bytes "
                 "[%0], [%1], %2, [%3];"
                 :: "r"(dst), "l"(src), "r"(bytes), "r"(mbar) : "memory");
}
__device__ __forceinline__ void mbar_wait(unsigned mbar, unsigned parity) {
    asm volatile(
        "{\n\t"
        ".reg .pred P;\n\t"
        "W_%=:\n\t"
        "mbarrier.try_wait.parity.acquire.cta.shared::cta.b64 P, [%0], %1, 0x989680;\n\t"
        "@P bra.uni D_%=;\n\t"
        "bra.uni W_%=;\n\t"
        "D_%=:\n\t"
        "}"
        :: "r"(mbar), "r"(parity) : "memory");
}

__global__ __launch_bounds__(NT, 1)
void detone(const float* __restrict__ Cls,
            const float* __restrict__ Shp,
            const float* __restrict__ Off,
            float* __restrict__ out)
{
    extern __shared__ float4 dyn[];          /* A = dyn[0..CF4), B = dyn[CF4..2CF4) */

    const int b   = blockIdx.x;
    const int tid = threadIdx.x;

    __shared__ int s_cnt;
    __shared__ unsigned long long s_mb[3];
    __shared__ union UU {
        unsigned hist[NBINS];                 /* 16 KB, fallback only */
        unsigned long long cand[CAND_FB];     /* 18.4 KB */
    } u;
    __shared__ int partial[NT];
    __shared__ int thr_bin;
    __shared__ int cand_cnt;
    __shared__ float s_score[TOPK];
    __shared__ float s_ctr[TOPK][3];
    __shared__ float s_ext[TOPK][3];
    __shared__ float s_lo[TOPK][3];
    __shared__ float s_hi[TOPK][3];
    __shared__ float s_vol[TOPK];
    __shared__ unsigned char s_valid[TOPK];
    __shared__ unsigned long long s_mask[TOPK];
    __shared__ unsigned long long s_keep;

    const float4* c4 = (const float4*)(Cls + (size_t)b * NA);
    const char*   gb = (const char*)c4;
    float* ob = out + (size_t)b * TOPK * 8;

    const unsigned sA  = smem_u32(dyn);
    const unsigned sB  = sA + CB;
    const unsigned mb0 = smem_u32(&s_mb[0]);
    const unsigned mb1 = smem_u32(&s_mb[1]);
    const unsigned mb2 = smem_u32(&s_mb[2]);

    if (tid == 0) {
        s_cnt = 0;
        mbar_init(mb0, 1);
        mbar_init(mb1, 1);
        mbar_init(mb2, 1);
    }
    if (tid < TOPK) s_mask[tid] = 0ull;
    if (tid < TOPK * 8) ob[tid] = -1.0f;     // prefill output
    __syncthreads();

    // ---- issue chunks 0 and 1 back-to-back: their DRAM drains overlap ----
    if (tid == 0) {
        mbar_expect_tx(mb0, CB);
        bulk_g2s(sA, gb, CB, mb0);
        mbar_expect_tx(mb1, CB);
        bulk_g2s(sB, gb + CB, CB, mb1);
    }

    // ---- per-chunk scan from smem ----
    auto process = [&](const float4* buf, int base_f4) {
        float4 p[JPT];
        #pragma unroll
        for (int j = 0; j < JPT; j++) p[j] = buf[j * NT + tid];
        unsigned hm = 0;
        #pragma unroll
        for (int j = 0; j < JPT; j++) {
            float mx = fmaxf(fmaxf(p[j].x, p[j].y), fmaxf(p[j].z, p[j].w));
            hm |= (mx > T_RAW) ? (1u << j) : 0u;
        }
        if (hm) {                             // rare (~4% of threads/chunk)
            #pragma unroll
            for (int j = 0; j < JPT; j++) {
                if (hm & (1u << j)) {
                    int gi = base_f4 + j * NT + tid;
                    #pragma unroll
                    for (int k = 0; k < 4; k++) {
                        float f = (k == 0) ? p[j].x : (k == 1) ? p[j].y
                                : (k == 2) ? p[j].z : p[j].w;
                        if (f > T_RAW) {
                            int off = atomicAdd(&s_cnt, 1);
                            if (off < CAND_FB) {
                                unsigned idx = (unsigned)(gi * 4 + k);
                                u.cand[off] =
                                    ((unsigned long long)fkey(f) << 32) | (unsigned)(~idx);
                            }
                        }
                    }
                }
            }
        }
    };

    mbar_wait(mb0, 0);
    process(dyn, 0);
    __syncthreads();                          // all done reading A

    if (tid == 0) {                           // chunk 2 into A while B processes
        mbar_expect_tx(mb2, CB);
        bulk_g2s(sA, gb + 2 * CB, CB, mb2);
    }
    mbar_wait(mb1, 0);
    process(dyn + CF4, CF4);

    mbar_wait(mb2, 0);
    process(dyn, 2 * CF4);
    __syncthreads();

    int c = s_cnt;
    const bool fast = (c >= TOPK) && (c <= NT) && (c <= CAND_FB);

    if (fast) {
        // ---------- FAST PATH: rank-select top-60, gather boxes ----------
        if (tid < c) {                                   // only active warps pay
            unsigned long long k0 = u.cand[tid];

            // scattered box loads issued NOW; overlap with the rank loop
            unsigned idx = ~(unsigned)(k0 & 0xFFFFFFFFull);
            int z = (int)idx / (Hh * Ww);
            int rem = (int)idx % (Hh * Ww);
            float az = (float)z, ay = (float)(rem / Ww), ax = (float)(rem % Ww);
            size_t base3 = (size_t)b * 3 * NA + idx;
            float o0 = Off[base3], o1 = Off[base3 + NA], o2 = Off[base3 + 2 * NA];
            float h0 = Shp[base3], h1 = Shp[base3 + NA], h2 = Shp[base3 + 2 * NA];

            int r0 = 0;
            #pragma unroll 4
            for (int j = 0; j < c; j++)                  // broadcast LDS
                r0 += (u.cand[j] > k0) ? 1 : 0;

            if (r0 < TOPK) {
                float raw = finv((unsigned)(k0 >> 32));
                float sc  = 1.0f / (1.0f + __expf(-raw));
                s_score[r0] = sc;
                s_valid[r0] = (sc > THRESH) ? 1 : 0;
                s_ctr[r0][0] = (az + o0) * 2.0f;         // stride = (2,2,2)
                s_ctr[r0][1] = (ay + o1) * 2.0f;
                s_ctr[r0][2] = (ax + o2) * 2.0f;
                s_ext[r0][0] = 2.0f * h0;
                s_ext[r0][1] = 2.0f * h1;
                s_ext[r0][2] = 2.0f * h2;
            }
        }
        __syncthreads();
    } else {
        // -------- exact histogram fallback, direct global reads (never hit) ------
        const int lane = tid & 31;
        for (int i = tid; i < NBINS; i += NT) u.hist[i] = 0u;
        if (tid == 0) { thr_bin = 0; cand_cnt = 0; }
        __syncthreads();
        for (int i = tid; i < NA / 4; i += NT) {
            float4 v = c4[i];
            #pragma unroll
            for (int k = 0; k < 4; k++) {
                float f = (k == 0) ? v.x : (k == 1) ? v.y : (k == 2) ? v.z : v.w;
                int bin = (int)(fkey(f) >> 20);
                unsigned m = __match_any_sync(0xFFFFFFFFu, bin);
                if (lane == (__ffs(m) - 1))
                    atomicAdd(&u.hist[bin], (unsigned)__popc(m));
            }
        }
        __syncthreads();
        const int BPT = NBINS / NT;                      // 4
        int hbase = tid * BPT;
        int loc = 0;
        #pragma unroll
        for (int j = 0; j < BPT; j++) loc += (int)u.hist[hbase + j];
        partial[tid] = loc;
        __syncthreads();
        if (tid == 0) {
            int run = 0;
            for (int t = NT - 1; t >= 0; t--) { int p = partial[t]; partial[t] = run; run += p; }
        }
        __syncthreads();
        {
            int cum_above = partial[tid];
            if (cum_above < TOPK && cum_above + loc >= TOPK) {
                int cum = cum_above;
                for (int j = BPT - 1; j >= 0; j--) {
                    cum += (int)u.hist[hbase + j];
                    if (cum >= TOPK) { thr_bin = hbase + j; break; }
                }
            }
        }
        __syncthreads();
        const unsigned klow = (unsigned)thr_bin << 20;
        __syncthreads();                                 // done with hist before reuse
        for (int i = tid; i < NA / 4; i += NT) {
            float4 v = c4[i];
            #pragma unroll
            for (int k = 0; k < 4; k++) {
                float f = (k == 0) ? v.x : (k == 1) ? v.y : (k == 2) ? v.z : v.w;
                unsigned key = fkey(f);
                if (key >= klow) {
                    int pos = atomicAdd(&cand_cnt, 1);
                    if (pos < CAND_FB) {
                        unsigned idx = (unsigned)(i * 4 + k);
                        u.cand[pos] = ((unsigned long long)key << 32) | (unsigned)(~idx);
                    }
                }
            }
        }
        __syncthreads();

        const int cf = min(cand_cnt, CAND_FB);
        for (int i = tid; i < cf; i += NT) {
            unsigned long long ki = u.cand[i];
            int rank = 0;
            for (int j = 0; j < cf; j++) rank += (u.cand[j] > ki) ? 1 : 0;
            if (rank < TOPK) {
                unsigned key = (unsigned)(ki >> 32);
                unsigned idx = ~(unsigned)(ki & 0xFFFFFFFFull);
                float raw = finv(key);
                float sc  = 1.0f / (1.0f + expf(-raw));
                s_score[rank] = sc;
                s_valid[rank] = (sc > THRESH) ? 1 : 0;
                int z   = (int)idx / (Hh * Ww);
                int rem = (int)idx % (Hh * Ww);
                int y   = rem / Ww;
                int x   = rem % Ww;
                size_t base3 = (size_t)b * 3 * NA + idx;
                float o0 = Off[base3], o1 = Off[base3 + NA], o2 = Off[base3 + 2 * NA];
                float h0 = Shp[base3], h1 = Shp[base3 + NA], h2 = Shp[base3 + 2 * NA];
                s_ctr[rank][0] = ((float)z + o0) * 2.0f;
                s_ctr[rank][1] = ((float)y + o1) * 2.0f;
                s_ctr[rank][2] = ((float)x + o2) * 2.0f;
                s_ext[rank][0] = 2.0f * h0;
                s_ext[rank][1] = 2.0f * h1;
                s_ext[rank][2] = 2.0f * h2;
            }
        }
        __syncthreads();
        // fallback also refills output (prefill happened before selection)
        if (tid < TOPK * 8) ob[tid] = -1.0f;
        __syncthreads();
    }

    // ---- precompute lo/hi/vol per box (one thread per box) ----
    if (tid < TOPK) {
        #pragma unroll
        for (int d = 0; d < 3; d++) {
            float cc = s_ctr[tid][d], ee = s_ext[tid][d];
            s_lo[tid][d] = cc - 0.5f * ee;
            s_hi[tid][d] = cc + 0.5f * ee;
        }
        s_vol[tid] = s_ext[tid][0] * s_ext[tid][1] * s_ext[tid][2];
    }
    __syncthreads();

    // ---- IoU > NMS_T bitmask: 17 strips x 4 cols per row ----
    {
        int i = tid % TOPK;           // row
        int qd = tid / TOPK;          // strip (tid < 1020 -> qd < 17)
        if (qd < 17) {
            float li0 = s_lo[i][0], li1 = s_lo[i][1], li2 = s_lo[i][2];
            float hi0 = s_hi[i][0], hi1 = s_hi[i][1], hi2 = s_hi[i][2];
            float vi  = s_vol[i];
            unsigned long long m = 0ull;
            int j0 = qd * 4;
            #pragma unroll
            for (int t = 0; t < 4; t++) {
                int j = j0 + t;
                if (j < TOPK) {
                    float d0 = fminf(hi0, s_hi[j][0]) - fmaxf(li0, s_lo[j][0]);
                    float d1 = fminf(hi1, s_hi[j][1]) - fmaxf(li1, s_lo[j][1]);
                    float d2 = fminf(hi2, s_hi[j][2]) - fmaxf(li2, s_lo[j][2]);
                    float inter = fmaxf(d0, 0.0f) * fmaxf(d1, 0.0f) * fmaxf(d2, 0.0f);
                    float un  = vi + s_vol[j] - inter;
                    float iou = inter / fmaxf(un, 1e-8f);
                    if (iou > NMS_T) m |= (1ull << j);
                }
            }
            if (m) atomicOr(&s_mask[i], m);
        }
    }
    __syncthreads();

    // ---- greedy NMS on a u64 mask ----
    if (tid == 0) {
        unsigned long long km = 0ull;
        #pragma unroll 4
        for (int i = 0; i < TOPK; i++)
            if (s_valid[i] && !(s_mask[i] & km)) km |= (1ull << i);
        s_keep = km;
    }
    __syncthreads();

    // ---- write kept rows at their rank (output already -1-filled) ----
    if (tid < TOPK) {
        unsigned long long km = s_keep;
        if ((km >> tid) & 1ull) {
            int rk = __popcll(km & ((1ull << tid) - 1ull));
            if (rk < NMS_TOPK) {
                float* row = ob + (size_t)rk * 8;
                row[0] = 1.0f;
                row[1] = s_score[tid];
                row[2] = s_ctr[tid][0];
                row[3] = s_ctr[tid][1];
                row[4] = s_ctr[tid][2];
                row[5] = s_ext[tid][0];
                row[6] = s_ext[tid][1];
                row[7] = s_ext[tid][2];
            }
        }
    }
}

extern "C" void kernel_launch(void* const* d_in, const int* in_sizes, int n_in,
                              void* d_out, int out_size)
{
    const float* Cls = (const float*)d_in[0];
    const float* Shp = (const float*)d_in[1];
    const float* Off = (const float*)d_in[2];
    float* out = (float*)d_out;

    cudaFuncSetAttribute(detone, cudaFuncAttributeMaxDynamicSharedMemorySize,
                         DYN_BYTES);
    detone<<<Bn, NT, DYN_BYTES>>>(Cls, Shp, Off, out);
}

// round 15
// speedup vs baseline: 1.2246x; 1.2246x over previous
#include <cuda_runtime.h>

#define Bn 64
#define Dd 32
#define Hh 48
#define Ww 48
#define NA (Dd*Hh*Ww)        /* 73728 anchors per batch */
#define TOPK 60
#define NMS_TOPK 20
#define THRESH 0.15f
#define NMS_T 0.05f
#define NBINS 4096
#define NT 1024
#define CHUNK 9              /* 2 rounds x 9 float4, MLP=9 */
#define CAND_FB 2304
#define WSLOT 32             /* staging slots per warp */
#define STG0 1280            /* staging base inside u.cand (1280+1024=2304) */
#define T_RAW 2.9f

__device__ __forceinline__ unsigned fkey(float f) {
    unsigned u = __float_as_uint(f);
    return u ^ ((u & 0x80000000u) ? 0xFFFFFFFFu : 0x80000000u);
}
__device__ __forceinline__ float finv(unsigned k) {
    unsigned u = (k & 0x80000000u) ? (k ^ 0x80000000u) : ~k;
    return __uint_as_float(u);
}

__global__ __launch_bounds__(NT, 1)
void detone(const float* __restrict__ Cls,
            const float* __restrict__ Shp,
            const float* __restrict__ Off,
            float* __restrict__ out)
{
    const int b   = blockIdx.x;
    const int tid = threadIdx.x;
    const int wid = tid >> 5;
    const int lid = tid & 31;

    __shared__ int s_wcnt[32];
    __shared__ int s_woff[32];
    __shared__ int s_cnt;
    __shared__ int s_ovf;
    __shared__ union UU {
        unsigned hist[NBINS];                 /* 16 KB, fallback only */
        unsigned long long cand[CAND_FB];     /* 18.4 KB: [0,1024) compact, [1280,2304) staging */
    } u;
    __shared__ int partial[NT];
    __shared__ int thr_bin;
    __shared__ int cand_cnt;
    __shared__ float s_score[TOPK];
    __shared__ float s_ctr[TOPK][3];
    __shared__ float s_ext[TOPK][3];
    __shared__ float s_lo[TOPK][3];
    __shared__ float s_hi[TOPK][3];
    __shared__ float s_vol[TOPK];
    __shared__ unsigned char s_valid[TOPK];
    __shared__ unsigned long long s_mask[TOPK];
    __shared__ unsigned long long s_keep;

    const float4* c4 = (const float4*)(Cls + (size_t)b * NA);
    float* ob = out + (size_t)b * TOPK * 8;

    if (tid < 32) s_wcnt[tid] = 0;
    if (tid < TOPK) s_mask[tid] = 0ull;

    // ---- round 1: 9 float4 -> registers ----
    float4 q[CHUNK];
    #pragma unroll
    for (int j = 0; j < CHUNK; j++) q[j] = c4[j * NT + tid];

    // prefill output with -1 while round-1 loads are in flight
    if (tid < TOPK * 8) ob[tid] = -1.0f;
    __syncthreads();                          // counters / s_mask init visible

    // ---- process round 1 (per-warp staging: spread-bank atomics) ----
    {
        unsigned hm = 0;
        #pragma unroll
        for (int j = 0; j < CHUNK; j++) {
            float mx = fmaxf(fmaxf(q[j].x, q[j].y), fmaxf(q[j].z, q[j].w));
            hm |= (mx > T_RAW) ? (1u << j) : 0u;
        }
        if (hm) {
            #pragma unroll
            for (int j = 0; j < CHUNK; j++) {
                if (hm & (1u << j)) {
                    int gi = j * NT + tid;
                    #pragma unroll
                    for (int k = 0; k < 4; k++) {
                        float f = (k == 0) ? q[j].x : (k == 1) ? q[j].y
                                : (k == 2) ? q[j].z : q[j].w;
                        if (f > T_RAW) {
                            int off = atomicAdd(&s_wcnt[wid], 1);
                            if (off < WSLOT) {
                                unsigned idx = (unsigned)(gi * 4 + k);
                                u.cand[STG0 + wid * WSLOT + off] =
                                    ((unsigned long long)fkey(f) << 32) | (unsigned)(~idx);
                            }
                        }
                    }
                }
            }
        }
    }

    // ---- round 2: 9 float4 -> registers ----
    #pragma unroll
    for (int j = 0; j < CHUNK; j++) q[j] = c4[(CHUNK + j) * NT + tid];
    {
        unsigned hm = 0;
        #pragma unroll
        for (int j = 0; j < CHUNK; j++) {
            float mx = fmaxf(fmaxf(q[j].x, q[j].y), fmaxf(q[j].z, q[j].w));
            hm |= (mx > T_RAW) ? (1u << j) : 0u;
        }
        if (hm) {
            #pragma unroll
            for (int j = 0; j < CHUNK; j++) {
                if (hm & (1u << j)) {
                    int gi = (CHUNK + j) * NT + tid;
                    #pragma unroll
                    for (int k = 0; k < 4; k++) {
                        float f = (k == 0) ? q[j].x : (k == 1) ? q[j].y
                                : (k == 2) ? q[j].z : q[j].w;
                        if (f > T_RAW) {
                            int off = atomicAdd(&s_wcnt[wid], 1);
                            if (off < WSLOT) {
                                unsigned idx = (unsigned)(gi * 4 + k);
                                u.cand[STG0 + wid * WSLOT + off] =
                                    ((unsigned long long)fkey(f) << 32) | (unsigned)(~idx);
                            }
                        }
                    }
                }
            }
        }
    }
    __syncthreads();

    // ---- prefix over warp counts (warp 0), detect overflow ----
    if (tid < 32) {
        int cnt = s_wcnt[tid];
        int ovf = (cnt > WSLOT) ? 1 : 0;
        int cl  = min(cnt, WSLOT);
        int inc = cl;
        #pragma unroll
        for (int d = 1; d < 32; d <<= 1) {        // inclusive scan
            int v = __shfl_up_sync(0xFFFFFFFFu, inc, d);
            if (tid >= d) inc += v;
        }
        s_woff[tid] = inc - cl;                   // exclusive
        if (tid == 31) s_cnt = inc;
        unsigned ob_ = __ballot_sync(0xFFFFFFFFu, ovf);
        if (tid == 0) s_ovf = (ob_ != 0u) ? 1 : 0;
    }
    __syncthreads();

    // ---- compact staging -> contiguous [0, c) ----
    {
        int w = wid, j = lid;
        int cw = min(s_wcnt[w], WSLOT);
        if (j < cw) u.cand[s_woff[w] + j] = u.cand[STG0 + w * WSLOT + j];
    }
    __syncthreads();

    int c = s_cnt;
    const bool fast = (!s_ovf) && (c >= TOPK) && (c <= NT);

    if (fast) {
        // ---------- FAST PATH: rank-select top-60, gather boxes ----------
        if (tid < c) {                                   // only active warps pay
            unsigned long long k0 = u.cand[tid];

            // scattered box loads issued NOW; overlap with the rank loop
            unsigned idx = ~(unsigned)(k0 & 0xFFFFFFFFull);
            int z = (int)idx / (Hh * Ww);
            int rem = (int)idx % (Hh * Ww);
            float az = (float)z, ay = (float)(rem / Ww), ax = (float)(rem % Ww);
            size_t base3 = (size_t)b * 3 * NA + idx;
            float o0 = Off[base3], o1 = Off[base3 + NA], o2 = Off[base3 + 2 * NA];
            float h0 = Shp[base3], h1 = Shp[base3 + NA], h2 = Shp[base3 + 2 * NA];

            int r0 = 0;
            #pragma unroll 4
            for (int j = 0; j < c; j++)                  // broadcast LDS
                r0 += (u.cand[j] > k0) ? 1 : 0;

            if (r0 < TOPK) {
                float raw = finv((unsigned)(k0 >> 32));
                float sc  = 1.0f / (1.0f + __expf(-raw));
                s_score[r0] = sc;
                s_valid[r0] = (sc > THRESH) ? 1 : 0;
                s_ctr[r0][0] = (az + o0) * 2.0f;         // stride = (2,2,2)
                s_ctr[r0][1] = (ay + o1) * 2.0f;
                s_ctr[r0][2] = (ax + o2) * 2.0f;
                s_ext[r0][0] = 2.0f * h0;
                s_ext[r0][1] = 2.0f * h1;
                s_ext[r0][2] = 2.0f * h2;
            }
        }
        __syncthreads();
    } else {
        // -------- exact histogram fallback (never hit on this data) --------
        for (int i = tid; i < NBINS; i += NT) u.hist[i] = 0u;
        if (tid == 0) { thr_bin = 0; cand_cnt = 0; }
        __syncthreads();
        for (int i = tid; i < NA / 4; i += NT) {
            float4 v = c4[i];
            #pragma unroll
            for (int k = 0; k < 4; k++) {
                float f = (k == 0) ? v.x : (k == 1) ? v.y : (k == 2) ? v.z : v.w;
                int bin = (int)(fkey(f) >> 20);
                unsigned m = __match_any_sync(0xFFFFFFFFu, bin);
                if (lid == (__ffs(m) - 1))
                    atomicAdd(&u.hist[bin], (unsigned)__popc(m));
            }
        }
        __syncthreads();
        const int BPT = NBINS / NT;                      // 4
        int hbase = tid * BPT;
        int loc = 0;
        #pragma unroll
        for (int j = 0; j < BPT; j++) loc += (int)u.hist[hbase + j];
        partial[tid] = loc;
        __syncthreads();
        if (tid == 0) {
            int run = 0;
            for (int t = NT - 1; t >= 0; t--) { int p = partial[t]; partial[t] = run; run += p; }
        }
        __syncthreads();
        {
            int cum_above = partial[tid];
            if (cum_above < TOPK && cum_above + loc >= TOPK) {
                int cum = cum_above;
                for (int j = BPT - 1; j >= 0; j--) {
                    cum += (int)u.hist[hbase + j];
                    if (cum >= TOPK) { thr_bin = hbase + j; break; }
                }
            }
        }
        __syncthreads();
        const unsigned klow = (unsigned)thr_bin << 20;
        __syncthreads();                                 // done with hist before reuse
        for (int i = tid; i < NA / 4; i += NT) {
            float4 v = c4[i];
            #pragma unroll
            for (int k = 0; k < 4; k++) {
                float f = (k == 0) ? v.x : (k == 1) ? v.y : (k == 2) ? v.z : v.w;
                unsigned key = fkey(f);
                if (key >= klow) {
                    int pos = atomicAdd(&cand_cnt, 1);
                    if (pos < CAND_FB) {
                        unsigned idx = (unsigned)(i * 4 + k);
                        u.cand[pos] = ((unsigned long long)key << 32) | (unsigned)(~idx);
                    }
                }
            }
        }
        __syncthreads();

        const int cf = min(cand_cnt, CAND_FB);
        for (int i = tid; i < cf; i += NT) {
            unsigned long long ki = u.cand[i];
            int rank = 0;
            for (int j = 0; j < cf; j++) rank += (u.cand[j] > ki) ? 1 : 0;
            if (rank < TOPK) {
                unsigned key = (unsigned)(ki >> 32);
                unsigned idx = ~(unsigned)(ki & 0xFFFFFFFFull);
                float raw = finv(key);
                float sc  = 1.0f / (1.0f + expf(-raw));
                s_score[rank] = sc;
                s_valid[rank] = (sc > THRESH) ? 1 : 0;
                int z   = (int)idx / (Hh * Ww);
                int rem = (int)idx % (Hh * Ww);
                int y   = rem / Ww;
                int x   = rem % Ww;
                size_t base3 = (size_t)b * 3 * NA + idx;
                float o0 = Off[base3], o1 = Off[base3 + NA], o2 = Off[base3 + 2 * NA];
                float h0 = Shp[base3], h1 = Shp[base3 + NA], h2 = Shp[base3 + 2 * NA];
                s_ctr[rank][0] = ((float)z + o0) * 2.0f;
                s_ctr[rank][1] = ((float)y + o1) * 2.0f;
                s_ctr[rank][2] = ((float)x + o2) * 2.0f;
                s_ext[rank][0] = 2.0f * h0;
                s_ext[rank][1] = 2.0f * h1;
                s_ext[rank][2] = 2.0f * h2;
            }
        }
        __syncthreads();
        // fallback also refills output (prefill happened before selection)
        if (tid < TOPK * 8) ob[tid] = -1.0f;
        __syncthreads();
    }

    // ---- precompute lo/hi/vol per box (one thread per box) ----
    if (tid < TOPK) {
        #pragma unroll
        for (int d = 0; d < 3; d++) {
            float cc = s_ctr[tid][d], ee = s_ext[tid][d];
            s_lo[tid][d] = cc - 0.5f * ee;
            s_hi[tid][d] = cc + 0.5f * ee;
        }
        s_vol[tid] = s_ext[tid][0] * s_ext[tid][1] * s_ext[tid][2];
    }
    __syncthreads();

    // ---- IoU > NMS_T bitmask: 17 strips x 4 cols per row ----
    {
        int i = tid % TOPK;           // row
        int qd = tid / TOPK;          // strip (tid < 1020 -> qd < 17)
        if (qd < 17) {
            float li0 = s_lo[i][0], li1 = s_lo[i][1], li2 = s_lo[i][2];
            float hi0 = s_hi[i][0], hi1 = s_hi[i][1], hi2 = s_hi[i][2];
            float vi  = s_vol[i];
            unsigned long long m = 0ull;
            int j0 = qd * 4;
            #pragma unroll
            for (int t = 0; t < 4; t++) {
                int j = j0 + t;
                if (j < TOPK) {
                    float d0 = fminf(hi0, s_hi[j][0]) - fmaxf(li0, s_lo[j][0]);
                    float d1 = fminf(hi1, s_hi[j][1]) - fmaxf(li1, s_lo[j][1]);
                    float d2 = fminf(hi2, s_hi[j][2]) - fmaxf(li2, s_lo[j][2]);
                    float inter = fmaxf(d0, 0.0f) * fmaxf(d1, 0.0f) * fmaxf(d2, 0.0f);
                    float un  = vi + s_vol[j] - inter;
                    float iou = inter / fmaxf(un, 1e-8f);
                    if (iou > NMS_T) m |= (1ull << j);
                }
            }
            if (m) atomicOr(&s_mask[i], m);
        }
    }
    __syncthreads();

    // ---- greedy NMS on a u64 mask ----
    if (tid == 0) {
        unsigned long long km = 0ull;
        #pragma unroll 4
        for (int i = 0; i < TOPK; i++)
            if (s_valid[i] && !(s_mask[i] & km)) km |= (1ull << i);
        s_keep = km;
    }
    __syncthreads();

    // ---- write kept rows at their rank (output already -1-filled) ----
    if (tid < TOPK) {
        unsigned long long km = s_keep;
        if ((km >> tid) & 1ull) {
            int rk = __popcll(km & ((1ull << tid) - 1ull));
            if (rk < NMS_TOPK) {
                float* row = ob + (size_t)rk * 8;
                row[0] = 1.0f;
                row[1] = s_score[tid];
                row[2] = s_ctr[tid][0];
                row[3] = s_ctr[tid][1];
                row[4] = s_ctr[tid][2];
                row[5] = s_ext[tid][0];
                row[6] = s_ext[tid][1];
                row[7] = s_ext[tid][2];
            }
        }
    }
}

extern "C" void kernel_launch(void* const* d_in, const int* in_sizes, int n_in,
                              void* d_out, int out_size)
{
    const float* Cls = (const float*)d_in[0];
    const float* Shp = (const float*)d_in[1];
    const float* Off = (const float*)d_in[2];
    float* out = (float*)d_out;

    detone<<<Bn, NT>>>(Cls, Shp, Off, out);
}

// round 16
// speedup vs baseline: 1.2272x; 1.0021x over previous
#include <cuda_runtime.h>

#define Bn 64
#define Dd 32
#define Hh 48
#define Ww 48
#define NA (Dd*Hh*Ww)        /* 73728 anchors per batch */
#define TOPK 60
#define NMS_TOPK 20
#define THRESH 0.15f
#define NMS_T 0.05f
#define NBINS 4096
#define NT 1024
#define CAND_FB 2304
#define WSLOT 32             /* staging slots per warp */
#define STG0 1280            /* staging base inside u.cand (1280+1024=2304) */
#define T_RAW 2.9f

__device__ __forceinline__ unsigned fkey(float f) {
    unsigned u = __float_as_uint(f);
    return u ^ ((u & 0x80000000u) ? 0xFFFFFFFFu : 0x80000000u);
}
__device__ __forceinline__ float finv(unsigned k) {
    unsigned u = (k & 0x80000000u) ? (k ^ 0x80000000u) : ~k;
    return __uint_as_float(u);
}

__global__ __launch_bounds__(NT, 1)
void detone(const float* __restrict__ Cls,
            const float* __restrict__ Shp,
            const float* __restrict__ Off,
            float* __restrict__ out)
{
    const int b   = blockIdx.x;
    const int tid = threadIdx.x;
    const int wid = tid >> 5;
    const int lid = tid & 31;

    __shared__ int s_wcnt[32];
    __shared__ int s_woff[32];
    __shared__ int s_cnt;
    __shared__ int s_ovf;
    __shared__ __align__(16) union UU {
        unsigned hist[NBINS];                 /* 16 KB, fallback only */
        unsigned long long cand[CAND_FB];     /* [0,1024) compact, [1280,2304) staging */
    } u;
    __shared__ int partial[NT];
    __shared__ int thr_bin;
    __shared__ int cand_cnt;
    __shared__ float s_score[TOPK];
    __shared__ float s_ctr[TOPK][3];
    __shared__ float s_ext[TOPK][3];
    __shared__ float s_lo[TOPK][3];
    __shared__ float s_hi[TOPK][3];
    __shared__ float s_vol[TOPK];
    __shared__ unsigned char s_valid[TOPK];
    __shared__ unsigned long long s_mask[TOPK];
    __shared__ unsigned long long s_keep;

    const float4* c4 = (const float4*)(Cls + (size_t)b * NA);
    float* ob = out + (size_t)b * TOPK * 8;

    if (tid < 32) s_wcnt[tid] = 0;
    if (tid < TOPK) s_mask[tid] = 0ull;

    // ---- per-group processor (per-warp spread-bank staging, R15-proven) ----
    auto process = [&](float4* r, int cnt, int basef4) {
        unsigned hm = 0;
        for (int j = 0; j < cnt; j++) {
            float mx = fmaxf(fmaxf(r[j].x, r[j].y), fmaxf(r[j].z, r[j].w));
            hm |= (mx > T_RAW) ? (1u << j) : 0u;
        }
        if (hm) {                                        // rare
            for (int j = 0; j < cnt; j++) {
                if (hm & (1u << j)) {
                    int gi = basef4 + j * NT + tid;
                    #pragma unroll
                    for (int k = 0; k < 4; k++) {
                        float f = (k == 0) ? r[j].x : (k == 1) ? r[j].y
                                : (k == 2) ? r[j].z : r[j].w;
                        if (f > T_RAW) {
                            int off = atomicAdd(&s_wcnt[wid], 1);
                            if (off < WSLOT) {
                                unsigned idx = (unsigned)(gi * 4 + k);
                                u.cand[STG0 + wid * WSLOT + off] =
                                    ((unsigned long long)fkey(f) << 32) | (unsigned)(~idx);
                            }
                        }
                    }
                }
            }
        }
    };

    // ================= pipelined scan: 5/5/5/3 with two register sets ============
    float4 A[5], B[5];
    #pragma unroll
    for (int j = 0; j < 5; j++) A[j] = c4[(0 + j) * NT + tid];
    #pragma unroll
    for (int j = 0; j < 5; j++) B[j] = c4[(5 + j) * NT + tid];

    // prefill output with -1 while loads are in flight
    if (tid < TOPK * 8) ob[tid] = -1.0f;
    __syncthreads();                          // counters / s_mask init visible

    process(A, 5, 0);                         // uses A; B draining
    #pragma unroll
    for (int j = 0; j < 5; j++) A[j] = c4[(10 + j) * NT + tid];   // refill A
    process(B, 5, 5 * NT);                    // uses B; A(10..14) draining
    #pragma unroll
    for (int j = 0; j < 3; j++) B[j] = c4[(15 + j) * NT + tid];   // refill B(3)
    process(A, 5, 10 * NT);
    process(B, 3, 15 * NT);
    __syncthreads();

    // ---- prefix over warp counts (warp 0), detect overflow ----
    if (tid < 32) {
        int cnt = s_wcnt[tid];
        int ovf = (cnt > WSLOT) ? 1 : 0;
        int cl  = min(cnt, WSLOT);
        int inc = cl;
        #pragma unroll
        for (int d = 1; d < 32; d <<= 1) {        // inclusive scan
            int v = __shfl_up_sync(0xFFFFFFFFu, inc, d);
            if (tid >= d) inc += v;
        }
        s_woff[tid] = inc - cl;                   // exclusive
        if (tid == 31) s_cnt = inc;
        unsigned ob_ = __ballot_sync(0xFFFFFFFFu, ovf);
        if (tid == 0) s_ovf = (ob_ != 0u) ? 1 : 0;
    }
    __syncthreads();

    // ---- compact staging -> contiguous [0, c); pad cand[c] = 0 for v2 rank ----
    {
        int cw = min(s_wcnt[wid], WSLOT);
        if (lid < cw) u.cand[s_woff[wid] + lid] = u.cand[STG0 + wid * WSLOT + lid];
        if (tid == 0) {
            int cc = s_cnt;
            if (cc < STG0) u.cand[cc] = 0ull;     // pad (key 0 < any real key)
        }
    }
    __syncthreads();

    int c = s_cnt;
    const bool fast = (!s_ovf) && (c >= TOPK) && (c <= NT);

    if (fast) {
        // ---------- FAST PATH: rank-select top-60, gather boxes ----------
        if (tid < c) {                                   // only active warps pay
            unsigned long long k0 = u.cand[tid];

            // scattered box loads issued NOW; overlap with the rank loop
            unsigned idx = ~(unsigned)(k0 & 0xFFFFFFFFull);
            int z = (int)idx / (Hh * Ww);
            int rem = (int)idx % (Hh * Ww);
            float az = (float)z, ay = (float)(rem / Ww), ax = (float)(rem % Ww);
            size_t base3 = (size_t)b * 3 * NA + idx;
            float o0 = Off[base3], o1 = Off[base3 + NA], o2 = Off[base3 + 2 * NA];
            float h0 = Shp[base3], h1 = Shp[base3 + NA], h2 = Shp[base3 + 2 * NA];

            // vectorized rank: 2 candidates per iteration (cand[c] padded)
            int r0 = 0;
            const ulonglong2* cv = (const ulonglong2*)u.cand;
            int half = (c + 1) >> 1;
            #pragma unroll 4
            for (int j = 0; j < half; j++) {
                ulonglong2 p = cv[j];
                r0 += (p.x > k0) ? 1 : 0;
                r0 += (p.y > k0) ? 1 : 0;
            }

            if (r0 < TOPK) {
                float raw = finv((unsigned)(k0 >> 32));
                float sc  = 1.0f / (1.0f + __expf(-raw));
                s_score[r0] = sc;
                s_valid[r0] = (sc > THRESH) ? 1 : 0;
                s_ctr[r0][0] = (az + o0) * 2.0f;         // stride = (2,2,2)
                s_ctr[r0][1] = (ay + o1) * 2.0f;
                s_ctr[r0][2] = (ax + o2) * 2.0f;
                s_ext[r0][0] = 2.0f * h0;
                s_ext[r0][1] = 2.0f * h1;
                s_ext[r0][2] = 2.0f * h2;
            }
        }
        __syncthreads();
    } else {
        // -------- exact histogram fallback (never hit on this data) --------
        for (int i = tid; i < NBINS; i += NT) u.hist[i] = 0u;
        if (tid == 0) { thr_bin = 0; cand_cnt = 0; }
        __syncthreads();
        for (int i = tid; i < NA / 4; i += NT) {
            float4 v = c4[i];
            #pragma unroll
            for (int k = 0; k < 4; k++) {
                float f = (k == 0) ? v.x : (k == 1) ? v.y : (k == 2) ? v.z : v.w;
                int bin = (int)(fkey(f) >> 20);
                unsigned m = __match_any_sync(0xFFFFFFFFu, bin);
                if (lid == (__ffs(m) - 1))
                    atomicAdd(&u.hist[bin], (unsigned)__popc(m));
            }
        }
        __syncthreads();
        const int BPT = NBINS / NT;                      // 4
        int hbase = tid * BPT;
        int loc = 0;
        #pragma unroll
        for (int j = 0; j < BPT; j++) loc += (int)u.hist[hbase + j];
        partial[tid] = loc;
        __syncthreads();
        if (tid == 0) {
            int run = 0;
            for (int t = NT - 1; t >= 0; t--) { int p = partial[t]; partial[t] = run; run += p; }
        }
        __syncthreads();
        {
            int cum_above = partial[tid];
            if (cum_above < TOPK && cum_above + loc >= TOPK) {
                int cum = cum_above;
                for (int j = BPT - 1; j >= 0; j--) {
                    cum += (int)u.hist[hbase + j];
                    if (cum >= TOPK) { thr_bin = hbase + j; break; }
                }
            }
        }
        __syncthreads();
        const unsigned klow = (unsigned)thr_bin << 20;
        __syncthreads();                                 // done with hist before reuse
        for (int i = tid; i < NA / 4; i += NT) {
            float4 v = c4[i];
            #pragma unroll
            for (int k = 0; k < 4; k++) {
                float f = (k == 0) ? v.x : (k == 1) ? v.y : (k == 2) ? v.z : v.w;
                unsigned key = fkey(f);
                if (key >= klow) {
                    int pos = atomicAdd(&cand_cnt, 1);
                    if (pos < CAND_FB) {
                        unsigned idx = (unsigned)(i * 4 + k);
                        u.cand[pos] = ((unsigned long long)key << 32) | (unsigned)(~idx);
                    }
                }
            }
        }
        __syncthreads();

        const int cf = min(cand_cnt, CAND_FB);
        for (int i = tid; i < cf; i += NT) {
            unsigned long long ki = u.cand[i];
            int rank = 0;
            for (int j = 0; j < cf; j++) rank += (u.cand[j] > ki) ? 1 : 0;
            if (rank < TOPK) {
                unsigned key = (unsigned)(ki >> 32);
                unsigned idx = ~(unsigned)(ki & 0xFFFFFFFFull);
                float raw = finv(key);
                float sc  = 1.0f / (1.0f + expf(-raw));
                s_score[rank] = sc;
                s_valid[rank] = (sc > THRESH) ? 1 : 0;
                int z   = (int)idx / (Hh * Ww);
                int rem = (int)idx % (Hh * Ww);
                int y   = rem / Ww;
                int x   = rem % Ww;
                size_t base3 = (size_t)b * 3 * NA + idx;
                float o0 = Off[base3], o1 = Off[base3 + NA], o2 = Off[base3 + 2 * NA];
                float h0 = Shp[base3], h1 = Shp[base3 + NA], h2 = Shp[base3 + 2 * NA];
                s_ctr[rank][0] = ((float)z + o0) * 2.0f;
                s_ctr[rank][1] = ((float)y + o1) * 2.0f;
                s_ctr[rank][2] = ((float)x + o2) * 2.0f;
                s_ext[rank][0] = 2.0f * h0;
                s_ext[rank][1] = 2.0f * h1;
                s_ext[rank][2] = 2.0f * h2;
            }
        }
        __syncthreads();
        // fallback also refills output (prefill happened before selection)
        if (tid < TOPK * 8) ob[tid] = -1.0f;
        __syncthreads();
    }

    // ---- precompute lo/hi/vol per box (one thread per box) ----
    if (tid < TOPK) {
        #pragma unroll
        for (int d = 0; d < 3; d++) {
            float cc = s_ctr[tid][d], ee = s_ext[tid][d];
            s_lo[tid][d] = cc - 0.5f * ee;
            s_hi[tid][d] = cc + 0.5f * ee;
        }
        s_vol[tid] = s_ext[tid][0] * s_ext[tid][1] * s_ext[tid][2];
    }
    __syncthreads();

    // ---- IoU > NMS_T bitmask: 17 strips x 4 cols per row ----
    {
        int i = tid % TOPK;           // row
        int qd = tid / TOPK;          // strip (tid < 1020 -> qd < 17)
        if (qd < 17) {
            float li0 = s_lo[i][0], li1 = s_lo[i][1], li2 = s_lo[i][2];
            float hi0 = s_hi[i][0], hi1 = s_hi[i][1], hi2 = s_hi[i][2];
            float vi  = s_vol[i];
            unsigned long long m = 0ull;
            int j0 = qd * 4;
            #pragma unroll
            for (int t = 0; t < 4; t++) {
                int j = j0 + t;
                if (j < TOPK) {
                    float d0 = fminf(hi0, s_hi[j][0]) - fmaxf(li0, s_lo[j][0]);
                    float d1 = fminf(hi1, s_hi[j][1]) - fmaxf(li1, s_lo[j][1]);
                    float d2 = fminf(hi2, s_hi[j][2]) - fmaxf(li2, s_lo[j][2]);
                    float inter = fmaxf(d0, 0.0f) * fmaxf(d1, 0.0f) * fmaxf(d2, 0.0f);
                    float un  = vi + s_vol[j] - inter;
                    float iou = inter / fmaxf(un, 1e-8f);
                    if (iou > NMS_T) m |= (1ull << j);
                }
            }
            if (m) atomicOr(&s_mask[i], m);
        }
    }
    __syncthreads();

    // ---- greedy NMS on a u64 mask ----
    if (tid == 0) {
        unsigned long long km = 0ull;
        #pragma unroll 4
        for (int i = 0; i < TOPK; i++)
            if (s_valid[i] && !(s_mask[i] & km)) km |= (1ull << i);
        s_keep = km;
    }
    __syncthreads();

    // ---- write kept rows at their rank (output already -1-filled) ----
    if (tid < TOPK) {
        unsigned long long km = s_keep;
        if ((km >> tid) & 1ull) {
            int rk = __popcll(km & ((1ull << tid) - 1ull));
            if (rk < NMS_TOPK) {
                float* row = ob + (size_t)rk * 8;
                row[0] = 1.0f;
                row[1] = s_score[tid];
                row[2] = s_ctr[tid][0];
                row[3] = s_ctr[tid][1];
                row[4] = s_ctr[tid][2];
                row[5] = s_ext[tid][0];
                row[6] = s_ext[tid][1];
                row[7] = s_ext[tid][2];
            }
        }
    }
}

extern "C" void kernel_launch(void* const* d_in, const int* in_sizes, int n_in,
                              void* d_out, int out_size)
{
    const float* Cls = (const float*)d_in[0];
    const float* Shp = (const float*)d_in[1];
    const float* Off = (const float*)d_in[2];
    float* out = (float*)d_out;

    detone<<<Bn, NT>>>(Cls, Shp, Off, out);
}